// round 8
// baseline (speedup 1.0000x reference)
#include <cuda_runtime.h>
#include <stdint.h>

#define N_POS 8192
#define N_NEG 4000u
#define N_TOT (N_POS + N_POS * (int)N_NEG)  // 32,776,192 (divisible by 4)
#define N_VEC (N_TOT / 4)                   // 8,194,048

#define HIST_WORDS (N_POS / 2)              // 4096 packed u16x2 words
#define HIST_PAD   32                       // 1 counter word per 128B L2 line

// Scratch (allocation-free rule: __device__ globals)
__device__ float          g_pos[N_POS];
__device__ unsigned short g_rowid[N_TOT];                // 65.55 MB
__device__ unsigned int   g_histp[HIST_WORDS * HIST_PAD]; // padded, 512 KB
__device__ unsigned int   g_done;

// ---------------------------------------------------------------------------
// Pass 1: scan idx (int32) once. Emit u16 row-id per element (0xFFFF = pos),
// scatter the 8192 pos values, zero padded hist + done counter.
// 131 MB read + 65.5 MB write -> DRAM-bound (~33 us measured).
// ---------------------------------------------------------------------------
__global__ void __launch_bounds__(256) mrr_pass1(
    const float* __restrict__ val, const int* __restrict__ idx)
{
    const unsigned int tid = blockIdx.x * blockDim.x + threadIdx.x;
    const unsigned int stride = gridDim.x * blockDim.x;

    for (unsigned int i = tid; i < HIST_WORDS * HIST_PAD; i += stride)
        g_histp[i] = 0u;
    if (tid == 0) g_done = 0u;

    const int4* __restrict__ idx4 = (const int4*)idx;
    ushort4* __restrict__ rid4 = (ushort4*)g_rowid;

    #pragma unroll 4
    for (unsigned int v = tid; v < N_VEC; v += stride) {
        int4 q = idx4[v];
        unsigned int j0 = (unsigned int)q.x;
        unsigned int j1 = (unsigned int)q.y;
        unsigned int j2 = (unsigned int)q.z;
        unsigned int j3 = (unsigned int)q.w;
        unsigned int base = v * 4u;

        ushort4 r;
        if (j0 < N_POS) { r.x = 0xFFFFu; g_pos[j0] = val[base + 0]; }
        else            { r.x = (unsigned short)((j0 - N_POS) / N_NEG); }
        if (j1 < N_POS) { r.y = 0xFFFFu; g_pos[j1] = val[base + 1]; }
        else            { r.y = (unsigned short)((j1 - N_POS) / N_NEG); }
        if (j2 < N_POS) { r.z = 0xFFFFu; g_pos[j2] = val[base + 2]; }
        else            { r.z = (unsigned short)((j2 - N_POS) / N_NEG); }
        if (j3 < N_POS) { r.w = 0xFFFFu; g_pos[j3] = val[base + 3]; }
        else            { r.w = (unsigned short)((j3 - N_POS) / N_NEG); }

        rid4[v] = r;
    }
}

// ---------------------------------------------------------------------------
// Pass 2: val4 + rowid4 (u16) streams, SMEM-privatized histogram with
// minority-side counting:
//   p >  0 -> count (v >  p);  p <= 0 -> count (v <= p)
// inc = (v > p) XOR (p <= 0); fixed up in finalize. Per-row count <= 4000 so
// packed u16 halves never overflow. Flush to PADDED global hist (one word
// per 128B line -> 4096 independent LTS queues, no serialization).
// Last-done block fuses the finalize. 48KB static smem -> 4 blocks/SM.
// ---------------------------------------------------------------------------
#define P2_BLOCKS 592
#define P2_THREADS 512

__global__ void __launch_bounds__(P2_THREADS) mrr_pass2(
    const float* __restrict__ val, float* __restrict__ out)
{
    __shared__ __align__(16) float s_pos[N_POS];   // 32768 B (reused in finalize)
    __shared__ unsigned int s_hist[HIST_WORDS];    // 16384 B
    __shared__ unsigned int s_is_last;

    const int t = threadIdx.x;
    for (int i = t; i < N_POS; i += P2_THREADS)      s_pos[i]  = g_pos[i];
    for (int i = t; i < HIST_WORDS; i += P2_THREADS) s_hist[i] = 0u;
    __syncthreads();

    const unsigned int tid = blockIdx.x * P2_THREADS + t;
    const unsigned int stride = gridDim.x * P2_THREADS;
    const float4*  __restrict__ v4 = (const float4*)val;
    const ushort4* __restrict__ r4 = (const ushort4*)g_rowid;

    #pragma unroll 2
    for (unsigned int v = tid; v < N_VEC; v += stride) {
        float4  f = v4[v];
        ushort4 r = r4[v];
        {
            float p = s_pos[r.x & 0x1FFFu];
            if (r.x != 0xFFFFu && ((f.x > p) != (p <= 0.0f)))
                atomicAdd(&s_hist[r.x >> 1], 1u << ((r.x & 1u) << 4));
        }
        {
            float p = s_pos[r.y & 0x1FFFu];
            if (r.y != 0xFFFFu && ((f.y > p) != (p <= 0.0f)))
                atomicAdd(&s_hist[r.y >> 1], 1u << ((r.y & 1u) << 4));
        }
        {
            float p = s_pos[r.z & 0x1FFFu];
            if (r.z != 0xFFFFu && ((f.z > p) != (p <= 0.0f)))
                atomicAdd(&s_hist[r.z >> 1], 1u << ((r.z & 1u) << 4));
        }
        {
            float p = s_pos[r.w & 0x1FFFu];
            if (r.w != 0xFFFFu && ((f.w > p) != (p <= 0.0f)))
                atomicAdd(&s_hist[r.w >> 1], 1u << ((r.w & 1u) << 4));
        }
    }
    __syncthreads();

    // Flush to padded global hist (whole-word add safe: per-row total <= 4000).
    for (int i = t; i < HIST_WORDS; i += P2_THREADS) {
        unsigned int h = s_hist[i];
        if (h) atomicAdd(&g_histp[i * HIST_PAD], h);
    }

    // Last-block-done election
    __threadfence();
    __syncthreads();
    if (t == 0) s_is_last = (atomicAdd(&g_done, 1u) == (unsigned)gridDim.x - 1u);
    __syncthreads();
    if (!s_is_last) return;

    // ---- Finalize (this block only) ----
    __threadfence();  // acquire all blocks' flushes
    double local = 0.0;
    float  samp[N_POS / P2_THREADS];  // 16 rows per thread
    #pragma unroll
    for (int k = 0; k < N_POS / P2_THREADS; k++) {
        int r = t + k * P2_THREADS;
        unsigned int h = g_histp[(r >> 1) * HIST_PAD];
        unsigned int c = (r & 1) ? (h >> 16) : (h & 0xFFFFu);
        float p = s_pos[r];           // still holds pos values
        unsigned int cnt_gt = (p > 0.0f) ? c : (N_NEG - c);
        float s = 1.0f / (float)(1u + cnt_gt);
        samp[k] = s;
        local += (double)s;
    }
    __syncthreads();                  // done reading s_pos; reuse as scratch
    #pragma unroll
    for (int k = 0; k < N_POS / P2_THREADS; k++)
        out[1 + t + k * P2_THREADS] = samp[k];

    double* ssum = (double*)s_pos;    // 512 doubles = 4KB
    ssum[t] = local;
    __syncthreads();
    for (int off = P2_THREADS / 2; off > 0; off >>= 1) {
        if (t < off) ssum[t] += ssum[t + off];
        __syncthreads();
    }
    if (t == 0) out[0] = (float)(ssum[0] / (double)N_POS);
}

extern "C" void kernel_launch(void* const* d_in, const int* in_sizes, int n_in,
                              void* d_out, int out_size)
{
    const float* val = (const float*)d_in[0];
    const int*   idx = (const int*)d_in[1];
    float*       out = (float*)d_out;

    mrr_pass1<<<2048, 256>>>(val, idx);
    mrr_pass2<<<P2_BLOCKS, P2_THREADS>>>(val, out);
}

// round 9
// speedup vs baseline: 1.1736x; 1.1736x over previous
#include <cuda_runtime.h>
#include <stdint.h>

#define N_POS 8192
#define N_NEG 4000u
#define N_TOT (N_POS + N_POS * (int)N_NEG)  // 32,776,192 (divisible by 4)
#define N_VEC (N_TOT / 4)                   // 8,194,048

#define HIST_WORDS (N_POS / 2)              // 4096 packed u16x2 words
#define HIST_PAD   32                       // 1 counter word per 128B L2 line

// Scratch (allocation-free rule: __device__ globals)
__device__ float          g_pos[N_POS];
__device__ unsigned short g_rowid[N_TOT];                 // 65.55 MB
__device__ unsigned int   g_histp[HIST_WORDS * HIST_PAD]; // padded, 512 KB

// ---------------------------------------------------------------------------
// Pass 1: scan idx (int32) once. Emit u16 row-id per element (0xFFFF = pos),
// scatter the 8192 pos values, zero the padded histogram.
// ---------------------------------------------------------------------------
__global__ void __launch_bounds__(256) mrr_pass1(
    const float* __restrict__ val, const int* __restrict__ idx)
{
    const unsigned int tid = blockIdx.x * blockDim.x + threadIdx.x;
    const unsigned int stride = gridDim.x * blockDim.x;

    for (unsigned int i = tid; i < HIST_WORDS * HIST_PAD; i += stride)
        g_histp[i] = 0u;

    const int4* __restrict__ idx4 = (const int4*)idx;
    ushort4* __restrict__ rid4 = (ushort4*)g_rowid;

    #pragma unroll 4
    for (unsigned int v = tid; v < N_VEC; v += stride) {
        int4 q = idx4[v];
        unsigned int j0 = (unsigned int)q.x;
        unsigned int j1 = (unsigned int)q.y;
        unsigned int j2 = (unsigned int)q.z;
        unsigned int j3 = (unsigned int)q.w;
        unsigned int base = v * 4u;

        ushort4 r;
        if (j0 < N_POS) { r.x = 0xFFFFu; g_pos[j0] = val[base + 0]; }
        else            { r.x = (unsigned short)((j0 - N_POS) / N_NEG); }
        if (j1 < N_POS) { r.y = 0xFFFFu; g_pos[j1] = val[base + 1]; }
        else            { r.y = (unsigned short)((j1 - N_POS) / N_NEG); }
        if (j2 < N_POS) { r.z = 0xFFFFu; g_pos[j2] = val[base + 2]; }
        else            { r.z = (unsigned short)((j2 - N_POS) / N_NEG); }
        if (j3 < N_POS) { r.w = 0xFFFFu; g_pos[j3] = val[base + 3]; }
        else            { r.w = (unsigned short)((j3 - N_POS) / N_NEG); }

        rid4[v] = r;
    }
}

// ---------------------------------------------------------------------------
// Pass 2: val4 + rowid4 (u16) streams (streaming loads), SMEM-privatized
// histogram with minority-side counting:
//   p >  0 -> count (v >  p);  p <= 0 -> count (v <= p)
// inc = (v > p) XOR (p <= 0); fixed up in pass 3. Per-row count <= 4000 so
// packed u16 halves never overflow. Flush to PADDED global hist (one word per
// 128B line). NO fence / NO election — kernel boundary provides ordering.
// 48KB static smem -> 4 blocks/SM, single wave of 592.
// ---------------------------------------------------------------------------
#define P2_BLOCKS 592
#define P2_THREADS 512

__global__ void __launch_bounds__(P2_THREADS) mrr_pass2(const float* __restrict__ val)
{
    __shared__ float        s_pos[N_POS];       // 32768 B
    __shared__ unsigned int s_hist[HIST_WORDS]; // 16384 B

    const int t = threadIdx.x;
    for (int i = t; i < N_POS; i += P2_THREADS)      s_pos[i]  = g_pos[i];
    for (int i = t; i < HIST_WORDS; i += P2_THREADS) s_hist[i] = 0u;
    __syncthreads();

    const unsigned int tid = blockIdx.x * P2_THREADS + t;
    const unsigned int stride = gridDim.x * P2_THREADS;
    const float4*  __restrict__ v4 = (const float4*)val;
    const ushort4* __restrict__ r4 = (const ushort4*)g_rowid;

    #pragma unroll 4
    for (unsigned int v = tid; v < N_VEC; v += stride) {
        float4  f = __ldcs(&v4[v]);
        ushort4 r = __ldcs(&r4[v]);
        {
            float p = s_pos[r.x & 0x1FFFu];
            if (r.x != 0xFFFFu && ((f.x > p) != (p <= 0.0f)))
                atomicAdd(&s_hist[r.x >> 1], 1u << ((r.x & 1u) << 4));
        }
        {
            float p = s_pos[r.y & 0x1FFFu];
            if (r.y != 0xFFFFu && ((f.y > p) != (p <= 0.0f)))
                atomicAdd(&s_hist[r.y >> 1], 1u << ((r.y & 1u) << 4));
        }
        {
            float p = s_pos[r.z & 0x1FFFu];
            if (r.z != 0xFFFFu && ((f.z > p) != (p <= 0.0f)))
                atomicAdd(&s_hist[r.z >> 1], 1u << ((r.z & 1u) << 4));
        }
        {
            float p = s_pos[r.w & 0x1FFFu];
            if (r.w != 0xFFFFu && ((f.w > p) != (p <= 0.0f)))
                atomicAdd(&s_hist[r.w >> 1], 1u << ((r.w & 1u) << 4));
        }
    }
    __syncthreads();

    // Flush to padded global hist (whole-word add safe: per-row total <= 4000).
    for (int i = t; i < HIST_WORDS; i += P2_THREADS)
        atomicAdd(&g_histp[i * HIST_PAD], s_hist[i]);
}

// ---------------------------------------------------------------------------
// Pass 3: undo minority-side flip, ranks -> sample_mrr, deterministic mean.
// out[0] = mrr, out[1..8192] = sample_mrr
// ---------------------------------------------------------------------------
__global__ void __launch_bounds__(1024) mrr_pass3(float* __restrict__ out)
{
    __shared__ double ssum[1024];
    const int t = threadIdx.x;
    double local = 0.0;
    for (int r = t; r < N_POS; r += 1024) {
        unsigned int h = g_histp[(r >> 1) * HIST_PAD];
        unsigned int c = (r & 1) ? (h >> 16) : (h & 0xFFFFu);
        float p = g_pos[r];
        unsigned int cnt_gt = (p > 0.0f) ? c : (N_NEG - c);
        float s = 1.0f / (float)(1u + cnt_gt);
        out[1 + r] = s;
        local += (double)s;
    }
    ssum[t] = local;
    __syncthreads();
    for (int off = 512; off > 0; off >>= 1) {
        if (t < off) ssum[t] += ssum[t + off];
        __syncthreads();
    }
    if (t == 0) out[0] = (float)(ssum[0] / (double)N_POS);
}

extern "C" void kernel_launch(void* const* d_in, const int* in_sizes, int n_in,
                              void* d_out, int out_size)
{
    const float* val = (const float*)d_in[0];
    const int*   idx = (const int*)d_in[1];
    float*       out = (float*)d_out;

    mrr_pass1<<<2048, 256>>>(val, idx);
    mrr_pass2<<<P2_BLOCKS, P2_THREADS>>>(val);
    mrr_pass3<<<1, 1024>>>(out);
}